// round 16
// baseline (speedup 1.0000x reference)
#include <cuda_runtime.h>

// ---------------------------------------------------------------------------
// LLG micromagnetics RK4 solver — halo-4 tiled persistent kernel,
// one thread per region cell (960 threads = 30 warps/SM for latency hiding).
//
// 256x256 grid. 128 blocks (16x8 block grid), each owns a 16x32 tile and
// processes a 24x40 region (halo 4 = one RK4 step's dependency radius).
// All 4 RK4 substages run block-locally in shared memory (shrinking pads
// 1..4). Inter-block sync: 8-neighbor flag handshake (st.release.gpu /
// ld.acquire.gpu) once per step, double-buffered global m.
// ---------------------------------------------------------------------------

namespace {
constexpr int NXC   = 256;
constexpr int NYC   = 256;
constexpr int NCELL = NXC * NYC;

constexpr int BGR  = 16;
constexpr int BGC  = 8;
constexpr int NBLK = BGR * BGC;      // 128
constexpr int TR   = 16;
constexpr int TC   = 32;
constexpr int HALO = 4;
constexpr int RH   = TR + 2 * HALO;  // 24
constexpr int RW   = TC + 2 * HALO;  // 40
constexpr int RCELLS = RH * RW;      // 960
constexpr int NTHR = RCELLS;         // 960 threads, 1 cell each

constexpr int TSTEPS = 256;
constexpr int NSRC   = 3;
constexpr int NPROBE = 5;
constexpr int NSIG   = 2;
constexpr int RELAX  = 100;
constexpr int TOTSTEPS = RELAX + NSIG * TSTEPS;  // 612

constexpr double GAMMA_LL = 175950000000.0;
constexpr double DT       = 5e-12;
constexpr double A_EXCH   = 3.5e-12;
constexpr double DX       = 5e-08;
constexpr double MU0      = 1.2566370614359172e-06;
constexpr float  CSOT     = 1e-4f;
constexpr float  HSTEP    = (float)(GAMMA_LL * DT);   // 0.87975
}

__device__ float    g_m[2][3][NCELL];      // ping-pong field buffers
__device__ float    g_mrel[3][NCELL];      // m_relaxed snapshot
__device__ unsigned g_flags[NBLK];         // per-block step counters
__device__ int      g_zero_int = 0;

// ---------------------------------------------------------------------------
__device__ __forceinline__ void evalk(
    const float* __restrict__ Sx, const float* __restrict__ Sy,
    const float* __restrict__ Sz,
    int u, int d, int l, int r,
    float sx, float sy, float sz,
    float bxv, float byv, float bzvv,
    float cex, float dzf, float negInv, float alpha,
    float& kx, float& ky, float& kz)
{
    float lx = Sx[u] + Sx[d] + Sx[l] + Sx[r] - 4.0f * sx;
    float ly = Sy[u] + Sy[d] + Sy[l] + Sy[r] - 4.0f * sy;
    float lz = Sz[u] + Sz[d] + Sz[l] + Sz[r] - 4.0f * sz;

    float Bx = fmaf(cex, lx, bxv);
    float By = fmaf(cex, ly, byv);
    float Bz = fmaf(dzf, sz, fmaf(cex, lz, bzvv));

    float c1x = sy * Bz - sz * By;
    float c1y = sz * Bx - sx * Bz;
    float c1z = sx * By - sy * Bx;
    float c2x = sy * c1z - sz * c1y;
    float c2y = sz * c1x - sx * c1z;
    float c2z = sx * c1y - sy * c1x;

    kx = fmaf(negInv, fmaf(alpha, c2x, c1x),  CSOT * (sx * sy));
    ky = fmaf(negInv, fmaf(alpha, c2y, c1y), -CSOT * fmaf(sx, sx, sz * sz));
    kz = fmaf(negInv, fmaf(alpha, c2z, c1z),  CSOT * (sy * sz));
}

// ---------------------------------------------------------------------------
__global__ void init_flags_kernel() {
    if (threadIdx.x < NBLK) g_flags[threadIdx.x] = 0u;
}

__global__ void __launch_bounds__(NTHR, 1) mm_solver_kernel(
    const float* __restrict__ sig,        // (NSIG, TSTEPS, NSRC) flat
    const float* __restrict__ Bext,       // (1, 3, NXC, NYC)
    const float* __restrict__ Msat_p,
    const int*   __restrict__ src_pos,    // (NSRC, 2)
    const int*   __restrict__ probe_pos,  // (NPROBE, 2)
    const int*   __restrict__ fb_p,
    float*       __restrict__ out)        // (NSIG, TSTEPS, NPROBE) flat
{
    __shared__ float s_m[3][RCELLS];
    __shared__ float s_a[3][RCELLS];
    __shared__ float s_b[3][RCELLS];

    const int tid = threadIdx.x;           // == region cell index, 0..959
    const int bid = blockIdx.x;
    const int br = bid >> 3, bc = bid & 7;
    const int org_r = br * TR - HALO;
    const int org_c = bc * TC - HALO;

    // polling threads 0..7 each own one neighbor block
    int nbid = -1;
    if (tid < 8) {
        const int dr8[8] = {-1,-1,-1, 0, 0, 1, 1, 1};
        const int dc8[8] = {-1, 0, 1,-1, 1,-1, 0, 1};
        int nr = br + dr8[tid], ncb = bc + dc8[tid];
        if (nr >= 0 && nr < BGR && ncb >= 0 && ncb < BGC)
            nbid = nr * BGC + ncb;
    }

    const float Msat = *Msat_p;
    const float cex  = (float)(2.0 * A_EXCH) / (Msat * (float)DX * (float)DX);
    const float dzf  = -(float)MU0 * Msat;
    const int   fb   = *fb_p;

    // ---- loop-invariant per-cell precompute ----
    const int lr = tid / RW, lc = tid - lr * RW;
    const int gr = org_r + lr, gc = org_c + lc;
    const int cr = min(max(gr, 0), NXC - 1);
    const int cc = min(max(gc, 0), NYC - 1);
    {
        // nothing
    }
    const int ur  = max(cr - 1, 0),  dw  = min(cr + 1, NXC - 1);
    const int lcl = max(cc - 1, 0),  rcl = min(cc + 1, NYC - 1);

    const int uN  = (ur - org_r) * RW + (cc  - org_c);
    const int dN  = (dw - org_r) * RW + (cc  - org_c);
    const int lN  = (cr - org_r) * RW + (lcl - org_c);
    const int rN  = (cr - org_r) * RW + (rcl - org_c);
    const int gld = cr * NYC + cc;

    const float bxv = Bext[0 * NCELL + gld];
    const float byv = Bext[1 * NCELL + gld];
    const float bz0 = Bext[2 * NCELL + gld];

    const int mpad = min(min(lr, RH - 1 - lr), min(lc, RW - 1 - lc));
    const bool own = (mpad >= HALO);

    int sid = -1;
    #pragma unroll
    for (int k = 0; k < NSRC; k++)
        if (src_pos[2 * k] == cr && src_pos[2 * k + 1] == cc) sid = k;
    int pid = -1;
    #pragma unroll
    for (int k = 0; k < NPROBE; k++)
        if (probe_pos[2 * k] == cr && probe_pos[2 * k + 1] == cc) pid = k;

    const float H  = HSTEP;
    const float H2 = 0.5f * HSTEP;
    const float H6 = HSTEP / 6.0f;

    float mx, my, mz;           // current m at this (clamped) cell
    float svx, svy, svz;        // current stage value (registers)
    float ax, ay, az;           // RK accumulator
    float pz0 = 0.0f;           // relaxed mz at probe

    for (int t = 0; t < TOTSTEPS; ++t) {
        const bool  driven = (t >= RELAX);
        const float alpha  = driven ? 0.01f : 0.5f;
        const float negInv = -1.0f / (1.0f + alpha * alpha);
        const int   rp     = t & 1;

        // ---- wait: 8 neighbors finished step t-1 (double-buffered m) ----
        if (t > 0) {
            if (nbid >= 0) {
                unsigned v;
                while (true) {
                    asm volatile("ld.acquire.gpu.b32 %0, [%1];"
                                 : "=r"(v) : "l"(&g_flags[nbid]) : "memory");
                    if ((int)v >= t) break;
                    __nanosleep(20);
                }
            }
            __syncthreads();
        }

        // ---- load region m into registers + s_m ----
        if (t == 0) {
            mx = 0.0f; my = 1.0f; mz = 0.0f;            // m0 = (0,1,0)
        } else if (t == RELAX + TSTEPS) {               // signal-1 reset
            mx = __ldcg(&g_mrel[0][gld]);
            my = __ldcg(&g_mrel[1][gld]);
            mz = __ldcg(&g_mrel[2][gld]);
        } else {
            mx = __ldcg(&g_m[rp][0][gld]);
            my = __ldcg(&g_m[rp][1][gld]);
            mz = __ldcg(&g_m[rp][2][gld]);
        }
        svx = mx; svy = my; svz = mz;
        s_m[0][tid] = mx; s_m[1][tid] = my; s_m[2][tid] = mz;

        float bzv = bz0;
        if (driven && sid >= 0)
            bzv += __ldg(&sig[(t - RELAX) * NSRC + sid]);
        __syncthreads();

        float kx, ky, kz;

        // ---- stage 1: k1 from s_m -> s_a (pad >= 1) ----
        if (mpad >= 1) {
            evalk(s_m[0], s_m[1], s_m[2], uN, dN, lN, rN,
                  svx, svy, svz, bxv, byv, bzv,
                  cex, dzf, negInv, alpha, kx, ky, kz);
            ax = kx; ay = ky; az = kz;
            svx = fmaf(H2, kx, mx); svy = fmaf(H2, ky, my); svz = fmaf(H2, kz, mz);
            s_a[0][tid] = svx; s_a[1][tid] = svy; s_a[2][tid] = svz;
        }
        __syncthreads();

        // ---- stage 2: k2 from s_a -> s_b (pad >= 2) ----
        if (mpad >= 2) {
            evalk(s_a[0], s_a[1], s_a[2], uN, dN, lN, rN,
                  svx, svy, svz, bxv, byv, bzv,
                  cex, dzf, negInv, alpha, kx, ky, kz);
            ax = fmaf(2.0f, kx, ax); ay = fmaf(2.0f, ky, ay); az = fmaf(2.0f, kz, az);
            svx = fmaf(H2, kx, mx); svy = fmaf(H2, ky, my); svz = fmaf(H2, kz, mz);
            s_b[0][tid] = svx; s_b[1][tid] = svy; s_b[2][tid] = svz;
        }
        __syncthreads();

        // ---- stage 3: k3 from s_b -> s_a (pad >= 3, full h) ----
        if (mpad >= 3) {
            evalk(s_b[0], s_b[1], s_b[2], uN, dN, lN, rN,
                  svx, svy, svz, bxv, byv, bzv,
                  cex, dzf, negInv, alpha, kx, ky, kz);
            ax = fmaf(2.0f, kx, ax); ay = fmaf(2.0f, ky, ay); az = fmaf(2.0f, kz, az);
            svx = fmaf(H, kx, mx); svy = fmaf(H, ky, my); svz = fmaf(H, kz, mz);
            s_a[0][tid] = svx; s_a[1][tid] = svy; s_a[2][tid] = svz;
        }
        __syncthreads();

        // ---- stage 4: k4 from s_a, combine, write global (owned only) ----
        if (own) {
            evalk(s_a[0], s_a[1], s_a[2], uN, dN, lN, rN,
                  svx, svy, svz, bxv, byv, bzv,
                  cex, dzf, negInv, alpha, kx, ky, kz);
            float nx = fmaf(H6, ax + kx, mx);
            float ny = fmaf(H6, ay + ky, my);
            float nz = fmaf(H6, az + kz, mz);
            __stcg(&g_m[rp ^ 1][0][gld], nx);   // owned: clamp == identity
            __stcg(&g_m[rp ^ 1][1][gld], ny);
            __stcg(&g_m[rp ^ 1][2][gld], nz);
            if (t == RELAX - 1) {               // m_relaxed snapshot (t=99)
                __stcg(&g_mrel[0][gld], nx);
                __stcg(&g_mrel[1][gld], ny);
                __stcg(&g_mrel[2][gld], nz);
                if (pid >= 0) pz0 = nz;
            }
            if (driven && pid >= 0) {
                float v = fb ? (nz - pz0) * Msat : nz;
                out[(t - RELAX) * NPROBE + pid] = v;
            }
        }

        // ---- publish step t complete (release; cumulative over barrier) ----
        __syncthreads();
        if (tid == 0) {
            unsigned nf = (unsigned)(t + 1);
            asm volatile("st.release.gpu.b32 [%0], %1;"
                         :: "l"(&g_flags[bid]), "r"(nf) : "memory");
        }
    }
}

// ---------------------------------------------------------------------------
extern "C" void kernel_launch(void* const* d_in, const int* in_sizes, int n_in,
                              void* d_out, int out_size) {
    (void)in_sizes; (void)out_size;
    const float* sig    = (const float*)d_in[0];
    const float* Bext   = (const float*)d_in[1];
    const float* Msat_p = (const float*)d_in[2];
    const int*   srcp   = (const int*)d_in[3];
    const int*   probep = (const int*)d_in[4];
    const int*   fbp;
    if (n_in > 5) {
        fbp = (const int*)d_in[5];
    } else {
        void* p = nullptr;
        cudaGetSymbolAddress(&p, g_zero_int);
        fbp = (const int*)p;
    }
    float* out = (float*)d_out;

    init_flags_kernel<<<1, NBLK>>>();
    mm_solver_kernel<<<NBLK, NTHR>>>(sig, Bext, Msat_p, srcp, probep, fbp, out);
}